// round 1
// baseline (speedup 1.0000x reference)
#include <cuda_runtime.h>
#include <math.h>

#define BATCH 4
#define CC 256
#define CI 128
#define NPIX 2304
#define BNEPS 1e-5f
#define NCHUNK 18
#define ETSPLIT 8   // e_time split-K chunks (2304/8 = 288, multiple of 16)

// ---------------- scratch (static device arrays; no allocation) ----------------
__device__ float g_PRE[4][BATCH][CI*NPIX];        // g11, g21, th1, ph1
__device__ float g_ETpart[BATCH][ETSPLIT][CI*CI];
__device__ float g_ET[BATCH][CI*CI];
__device__ float g_A1[BATCH][CI*CI];              // et2s
__device__ float g_A2[BATCH][CI*CI];              // et1s
__device__ float g_E[BATCH][NPIX*NPIX];           // e_space (85MB)
__device__ float g_Z[2][BATCH][CI*NPIX];
__device__ float g_Y[2][BATCH][CI*NPIX];
__device__ float g_colmax[BATCH][NPIX];
__device__ float g_colrsum[BATCH][NPIX];
__device__ float g_rowmax[BATCH][NPIX];
__device__ float g_rowrsum[BATCH][NPIX];
__device__ float g_pmax[BATCH][NCHUNK][NPIX];
__device__ float g_psum[BATCH][NCHUNK][NPIX];
__device__ float g_Wpre[4][CI*CC];
__device__ float g_bpre[4][CI];
__device__ float g_Wpost[2][CC*CI];
__device__ float g_bpost[2][CC];

// ---------------- BN folding ----------------
__global__ void k_fold(const float* __restrict__ bn_pre, const float* __restrict__ w_pre,
                       const float* __restrict__ b_pre, const float* __restrict__ w_post,
                       const float* __restrict__ b_post, const float* __restrict__ bn_post)
{
    int tid = threadIdx.x;
    if (blockIdx.x == 0) {
        // pre: fold BN into conv weight: y = W diag(s) x + (W t + b)
        int i = tid >> 7, o = tid & 127;
        const float* bp = bn_pre + i * 4 * CC;
        const float* w  = w_pre + (i * CI + o) * CC;
        float acc = b_pre[i * CI + o];
        for (int c = 0; c < CC; c++) {
            float s = bp[c] * rsqrtf(bp[3 * CC + c] + BNEPS);
            float t = bp[CC + c] - bp[2 * CC + c] * s;
            float wv = w[c];
            g_Wpre[i][o * CC + c] = wv * s;
            acc += wv * t;
        }
        g_bpre[i][o] = acc;
    } else {
        // post: BN after conv: out = s*(Wy + b) + (beta - mean*s)
        int i = tid >> 8, o = tid & 255;
        const float* bp = bn_post + i * 4 * CC;
        float s = bp[o] * rsqrtf(bp[3 * CC + o] + BNEPS);
        const float* w = w_post + (i * CC + o) * CI;
        for (int c = 0; c < CI; c++)
            g_Wpost[i][o * CI + c] = w[c] * s;
        g_bpost[i][o] = b_post[i * CC + o] * s + bp[CC + o] - bp[2 * CC + o] * s;
    }
}

// ---------------- shared GEMM cores (64x64x16 tile, 256 thr, 4x4 microtile) ----------------
__device__ __forceinline__ void mm16(float acc[4][4], const float ar[4], const float br[4])
{
#pragma unroll
    for (int r = 0; r < 4; r++)
#pragma unroll
        for (int c2 = 0; c2 < 4; c2++)
            acc[r][c2] = fmaf(ar[r], br[c2], acc[r][c2]);
}

// C = A(row-major, [M,K]) * B(row-major, [K,N]) tile
__device__ __forceinline__ void nn_core64(const float* __restrict__ A, int lda,
                                          const float* __restrict__ Bm, int ldb,
                                          int K, int m0, int n0, float acc[4][4])
{
    __shared__ float As[16][68];
    __shared__ float Bs[16][64];
    const int tid = threadIdx.x;
    const int tx = tid & 15, ty = tid >> 4;
    const int ai = tid >> 2, aq = tid & 3;
    const int bk = tid >> 4, bj = (tid & 15) * 4;
    for (int k0 = 0; k0 < K; k0 += 16) {
        float4 av = *(const float4*)&A[(m0 + ai) * lda + k0 + aq * 4];
        As[aq*4+0][ai] = av.x; As[aq*4+1][ai] = av.y; As[aq*4+2][ai] = av.z; As[aq*4+3][ai] = av.w;
        *(float4*)&Bs[bk][bj] = *(const float4*)&Bm[(k0 + bk) * ldb + n0 + bj];
        __syncthreads();
#pragma unroll
        for (int k = 0; k < 16; k++) {
            float4 a4 = *(const float4*)&As[k][ty * 4];
            float4 b4 = *(const float4*)&Bs[k][tx * 4];
            float ar[4] = {a4.x, a4.y, a4.z, a4.w};
            float br[4] = {b4.x, b4.y, b4.z, b4.w};
            mm16(acc, ar, br);
        }
        __syncthreads();
    }
}

// C[i,j] = sum_k A[m0+i,k] * B[n0+j,k]  (both row-major, K along rows)
__device__ __forceinline__ void nt_core64(const float* __restrict__ A,
                                          const float* __restrict__ Bm, int ld,
                                          int kbeg, int kend, int m0, int n0, float acc[4][4])
{
    __shared__ float As[16][68];
    __shared__ float Bs[16][68];
    const int tid = threadIdx.x;
    const int tx = tid & 15, ty = tid >> 4;
    const int ri = tid >> 2, rq = tid & 3;
    for (int k0 = kbeg; k0 < kend; k0 += 16) {
        float4 av = *(const float4*)&A[(m0 + ri) * ld + k0 + rq * 4];
        As[rq*4+0][ri] = av.x; As[rq*4+1][ri] = av.y; As[rq*4+2][ri] = av.z; As[rq*4+3][ri] = av.w;
        float4 bv = *(const float4*)&Bm[(n0 + ri) * ld + k0 + rq * 4];
        Bs[rq*4+0][ri] = bv.x; Bs[rq*4+1][ri] = bv.y; Bs[rq*4+2][ri] = bv.z; Bs[rq*4+3][ri] = bv.w;
        __syncthreads();
#pragma unroll
        for (int k = 0; k < 16; k++) {
            float4 a4 = *(const float4*)&As[k][ty * 4];
            float4 b4 = *(const float4*)&Bs[k][tx * 4];
            float ar[4] = {a4.x, a4.y, a4.z, a4.w};
            float br[4] = {b4.x, b4.y, b4.z, b4.w};
            mm16(acc, ar, br);
        }
        __syncthreads();
    }
}

// C[i,j] = sum_k A[k, m0+i] * B[k, n0+j]  (both row-major [K, ld])
__device__ __forceinline__ void tn_core64(const float* __restrict__ A,
                                          const float* __restrict__ Bm, int ld,
                                          int K, int m0, int n0, float acc[4][4])
{
    __shared__ float As[16][64];
    __shared__ float Bs[16][64];
    const int tid = threadIdx.x;
    const int tx = tid & 15, ty = tid >> 4;
    const int lk = tid >> 4, lj = (tid & 15) * 4;
    for (int k0 = 0; k0 < K; k0 += 16) {
        *(float4*)&As[lk][lj] = *(const float4*)&A[(k0 + lk) * ld + m0 + lj];
        *(float4*)&Bs[lk][lj] = *(const float4*)&Bm[(k0 + lk) * ld + n0 + lj];
        __syncthreads();
#pragma unroll
        for (int k = 0; k < 16; k++) {
            float4 a4 = *(const float4*)&As[k][ty * 4];
            float4 b4 = *(const float4*)&Bs[k][tx * 4];
            float ar[4] = {a4.x, a4.y, a4.z, a4.w};
            float br[4] = {b4.x, b4.y, b4.z, b4.w};
            mm16(acc, ar, br);
        }
        __syncthreads();
    }
}

// ---------------- pre GEMMs: PRE[i][b] = Wpre[i] @ x + bpre[i] ----------------
__global__ void __launch_bounds__(256) k_pre(const float* __restrict__ x1, const float* __restrict__ x2)
{
    int i = blockIdx.z >> 2, b = blockIdx.z & 3;
    int m0 = blockIdx.y * 64, n0 = blockIdx.x * 64;
    const float* Bm = ((i & 1) ? x2 : x1) + b * CC * NPIX;
    float acc[4][4] = {};
    nn_core64(g_Wpre[i], CC, Bm, NPIX, CC, m0, n0, acc);
    int tx = threadIdx.x & 15, ty = threadIdx.x >> 4;
    float* Cout = g_PRE[i][b];
#pragma unroll
    for (int r = 0; r < 4; r++) {
        int row = m0 + ty * 4 + r;
        float bias = g_bpre[i][row];
#pragma unroll
        for (int c2 = 0; c2 < 4; c2++)
            Cout[row * NPIX + n0 + tx * 4 + c2] = acc[r][c2] + bias;
    }
}

// ---------------- e_time = T @ P^T, split-K partials ----------------
__global__ void __launch_bounds__(256) k_etime()
{
    int b = blockIdx.z >> 3, ks = blockIdx.z & 7;
    int m0 = blockIdx.y * 64, n0 = blockIdx.x * 64;
    float acc[4][4] = {};
    const int chunk = NPIX / ETSPLIT; // 288
    nt_core64(g_PRE[2][b], g_PRE[3][b], NPIX, ks * chunk, ks * chunk + chunk, m0, n0, acc);
    int tx = threadIdx.x & 15, ty = threadIdx.x >> 4;
    float* outp = g_ETpart[b][ks];
#pragma unroll
    for (int r = 0; r < 4; r++)
#pragma unroll
        for (int c2 = 0; c2 < 4; c2++)
            outp[(m0 + ty * 4 + r) * CI + n0 + tx * 4 + c2] = acc[r][c2];
}

__global__ void k_etreduce()
{
    int b = blockIdx.y, idx = blockIdx.x * 256 + threadIdx.x;
    float s = 0.f;
#pragma unroll
    for (int p = 0; p < ETSPLIT; p++) s += g_ETpart[b][p][idx];
    g_ET[b][idx] = s;
}

// ---------------- e_time softmaxes: A1 = et2s, A2 = et1s ----------------
__global__ void k_softmax_time()
{
    int b = blockIdx.x, t = threadIdx.x;
    const float* ET = g_ET[b];
    // row softmax of ET -> A2[t][:]
    float mx = -3.0e38f;
    for (int d = 0; d < CI; d++) mx = fmaxf(mx, ET[t * CI + d]);
    float s = 0.f;
    for (int d = 0; d < CI; d++) s += __expf(ET[t * CI + d] - mx);
    float rs = 1.f / s;
    for (int d = 0; d < CI; d++) g_A2[b][t * CI + d] = __expf(ET[t * CI + d] - mx) * rs;
    // column softmax of ET (column t) -> A1[t][:]  (A1[c,d] = exp(ET[d,c]-max)/sum)
    mx = -3.0e38f;
    for (int d = 0; d < CI; d++) mx = fmaxf(mx, ET[d * CI + t]);
    s = 0.f;
    for (int d = 0; d < CI; d++) s += __expf(ET[d * CI + t] - mx);
    rs = 1.f / s;
    for (int d = 0; d < CI; d++) g_A1[b][t * CI + d] = __expf(ET[d * CI + t] - mx) * rs;
}

// ---------------- Z GEMMs: Z1 = A1@G1, Z2 = A2@G2 ----------------
__global__ void __launch_bounds__(256) k_zgemm()
{
    int zi = blockIdx.z >> 2, b = blockIdx.z & 3;
    int m0 = blockIdx.y * 64, n0 = blockIdx.x * 64;
    const float* A = zi ? g_A2[b] : g_A1[b];
    float acc[4][4] = {};
    nn_core64(A, CI, g_PRE[zi][b], NPIX, CI, m0, n0, acc);
    int tx = threadIdx.x & 15, ty = threadIdx.x >> 4;
    float* Zout = g_Z[zi][b];
#pragma unroll
    for (int r = 0; r < 4; r++)
#pragma unroll
        for (int c2 = 0; c2 < 4; c2++)
            Zout[(m0 + ty * 4 + r) * NPIX + n0 + tx * 4 + c2] = acc[r][c2];
}

// ---------------- e_space[n,m] = sum_c T[c,n] P[c,m] ----------------
__global__ void __launch_bounds__(256) k_espace()
{
    int b = blockIdx.z;
    int m0 = blockIdx.y * 64;   // n (output row)
    int n0 = blockIdx.x * 64;   // m (output col)
    float acc[4][4] = {};
    tn_core64(g_PRE[2][b], g_PRE[3][b], NPIX, CI, m0, n0, acc);
    int tx = threadIdx.x & 15, ty = threadIdx.x >> 4;
    float* Ep = g_E[b];
#pragma unroll
    for (int r = 0; r < 4; r++)
#pragma unroll
        for (int c2 = 0; c2 < 4; c2++)
            Ep[(m0 + ty * 4 + r) * NPIX + n0 + tx * 4 + c2] = acc[r][c2];
}

// ---------------- e_space column stats (softmax over n, per column m) ----------------
__global__ void k_colpart()
{
    int b = blockIdx.z, ch = blockIdx.y;
    int m = blockIdx.x * 256 + threadIdx.x;
    const float* Ep = g_E[b];
    float mx = -3.0e38f, s = 0.f;
    int n0 = ch * (NPIX / NCHUNK);
    for (int n = n0; n < n0 + NPIX / NCHUNK; n++) {
        float v = Ep[n * NPIX + m];
        if (v > mx) { s = s * __expf(mx - v) + 1.f; mx = v; }
        else        { s += __expf(v - mx); }
    }
    g_pmax[b][ch][m] = mx;
    g_psum[b][ch][m] = s;
}

__global__ void k_colreduce()
{
    int b = blockIdx.y, m = blockIdx.x * 256 + threadIdx.x;
    float mx = -3.0e38f, s = 0.f;
#pragma unroll
    for (int ch = 0; ch < NCHUNK; ch++) {
        float pm = g_pmax[b][ch][m], ps = g_psum[b][ch][m];
        float nm = fmaxf(mx, pm);
        s = s * __expf(mx - nm) + ps * __expf(pm - nm);
        mx = nm;
    }
    g_colmax[b][m] = mx;
    g_colrsum[b][m] = 1.f / s;
}

// ---------------- e_space row stats (softmax over m, per row n) ----------------
__global__ void k_rowstats()
{
    int b = blockIdx.y;
    int n = blockIdx.x * 8 + (threadIdx.x >> 5);
    int lane = threadIdx.x & 31;
    const float* row = g_E[b] + n * NPIX;
    float mx = -3.0e38f, s = 0.f;
    for (int m = lane; m < NPIX; m += 32) {
        float v = row[m];
        if (v > mx) { s = s * __expf(mx - v) + 1.f; mx = v; }
        else        { s += __expf(v - mx); }
    }
#pragma unroll
    for (int off = 16; off; off >>= 1) {
        float om = __shfl_xor_sync(0xffffffffu, mx, off);
        float os = __shfl_xor_sync(0xffffffffu, s, off);
        float nm = fmaxf(mx, om);
        s = s * __expf(mx - nm) + os * __expf(om - nm);
        mx = nm;
    }
    if (lane == 0) { g_rowmax[b][n] = mx; g_rowrsum[b][n] = 1.f / s; }
}

// ---------------- Y GEMMs with fused softmax B-load (BM=128, BN=64, BK=16) ----------------
__global__ void __launch_bounds__(256) k_ygemm()
{
    int yi = blockIdx.z >> 2, b = blockIdx.z & 3;
    const float* __restrict__ A    = g_Z[yi][b];
    const float* __restrict__ Ep   = g_E[b];
    const float* __restrict__ vmax = yi ? g_rowmax[b]  : g_colmax[b];
    const float* __restrict__ vrs  = yi ? g_rowrsum[b] : g_colrsum[b];
    int m0 = blockIdx.x * 64;
    __shared__ float As[16][132];
    __shared__ float Bs[16][68];
    int tid = threadIdx.x;
    int tx = tid & 15, ty = tid >> 4;
    int ai = tid >> 1, aq = tid & 1;
    float acc[8][4] = {};

    int bk = tid >> 4, bj = (tid & 15) * 4;   // yi==0 load pattern
    int bjj = tid & 63, bq = tid >> 6;        // yi==1 load pattern
    float mx0, mx1, mx2, mx3;
    if (yi == 0) {
        mx0 = vmax[m0 + bj];     mx1 = vmax[m0 + bj + 1];
        mx2 = vmax[m0 + bj + 2]; mx3 = vmax[m0 + bj + 3];
    } else {
        mx0 = vmax[m0 + bjj]; mx1 = mx2 = mx3 = mx0;
    }

    for (int k0 = 0; k0 < NPIX; k0 += 16) {
        float4 a0 = *(const float4*)&A[ai * NPIX + k0 + aq * 8];
        float4 a1 = *(const float4*)&A[ai * NPIX + k0 + aq * 8 + 4];
        As[aq*8+0][ai] = a0.x; As[aq*8+1][ai] = a0.y; As[aq*8+2][ai] = a0.z; As[aq*8+3][ai] = a0.w;
        As[aq*8+4][ai] = a1.x; As[aq*8+5][ai] = a1.y; As[aq*8+6][ai] = a1.z; As[aq*8+7][ai] = a1.w;
        if (yi == 0) {
            // Bs[k][j] = exp(E[n=k0+k, m0+j] - colmax[m0+j])
            float4 e = *(const float4*)&Ep[(k0 + bk) * NPIX + m0 + bj];
            Bs[bk][bj + 0] = __expf(e.x - mx0);
            Bs[bk][bj + 1] = __expf(e.y - mx1);
            Bs[bk][bj + 2] = __expf(e.z - mx2);
            Bs[bk][bj + 3] = __expf(e.w - mx3);
        } else {
            // Bs[k][j] = exp(E[m0+j, n=k0+k] - rowmax[m0+j])
            float4 e = *(const float4*)&Ep[(m0 + bjj) * NPIX + k0 + bq * 4];
            Bs[bq*4+0][bjj] = __expf(e.x - mx0);
            Bs[bq*4+1][bjj] = __expf(e.y - mx0);
            Bs[bq*4+2][bjj] = __expf(e.z - mx0);
            Bs[bq*4+3][bjj] = __expf(e.w - mx0);
        }
        __syncthreads();
#pragma unroll
        for (int k = 0; k < 16; k++) {
            float4 aA = *(const float4*)&As[k][ty * 8];
            float4 aB = *(const float4*)&As[k][ty * 8 + 4];
            float4 b4 = *(const float4*)&Bs[k][tx * 4];
            float ar[8] = {aA.x, aA.y, aA.z, aA.w, aB.x, aB.y, aB.z, aB.w};
            float br[4] = {b4.x, b4.y, b4.z, b4.w};
#pragma unroll
            for (int r = 0; r < 8; r++)
#pragma unroll
                for (int c2 = 0; c2 < 4; c2++)
                    acc[r][c2] = fmaf(ar[r], br[c2], acc[r][c2]);
        }
        __syncthreads();
    }
    float* Yp = g_Y[yi][b];
#pragma unroll
    for (int r = 0; r < 8; r++) {
        int row = ty * 8 + r;
#pragma unroll
        for (int c2 = 0; c2 < 4; c2++) {
            int m = m0 + tx * 4 + c2;
            Yp[row * NPIX + m] = acc[r][c2] * vrs[m];
        }
    }
}

// ---------------- post GEMM + bias + residual -> d_out ----------------
__global__ void __launch_bounds__(256) k_post(const float* __restrict__ x1,
                                              const float* __restrict__ x2,
                                              float* __restrict__ out)
{
    int i = blockIdx.z >> 2, b = blockIdx.z & 3;
    int m0 = blockIdx.y * 64, n0 = blockIdx.x * 64;
    float acc[4][4] = {};
    nn_core64(g_Wpost[i], CI, g_Y[i][b], NPIX, CI, m0, n0, acc);
    int tx = threadIdx.x & 15, ty = threadIdx.x >> 4;
    const float* xs = (i ? x2 : x1) + b * CC * NPIX;
    float* op = out + (size_t)i * BATCH * CC * NPIX + (size_t)b * CC * NPIX;
#pragma unroll
    for (int r = 0; r < 4; r++) {
        int row = m0 + ty * 4 + r;
        float bias = g_bpost[i][row];
#pragma unroll
        for (int c2 = 0; c2 < 4; c2++) {
            int col = n0 + tx * 4 + c2;
            op[row * NPIX + col] = acc[r][c2] + bias + xs[row * NPIX + col];
        }
    }
}

// ---------------- launcher ----------------
extern "C" void kernel_launch(void* const* d_in, const int* in_sizes, int n_in,
                              void* d_out, int out_size)
{
    const float* x1      = (const float*)d_in[0];
    const float* x2      = (const float*)d_in[1];
    const float* bn_pre  = (const float*)d_in[2];
    const float* w_pre   = (const float*)d_in[3];
    const float* b_pre   = (const float*)d_in[4];
    const float* w_post  = (const float*)d_in[5];
    const float* b_post  = (const float*)d_in[6];
    const float* bn_post = (const float*)d_in[7];
    float* out = (float*)d_out;

    k_fold<<<2, 512>>>(bn_pre, w_pre, b_pre, w_post, b_post, bn_post);
    k_pre<<<dim3(36, 2, 16), 256>>>(x1, x2);
    k_etime<<<dim3(2, 2, BATCH * ETSPLIT), 256>>>();
    k_etreduce<<<dim3(64, BATCH), 256>>>();
    k_softmax_time<<<BATCH, 128>>>();
    k_espace<<<dim3(36, 36, BATCH), 256>>>();
    k_zgemm<<<dim3(36, 2, 8), 256>>>();
    k_colpart<<<dim3(9, NCHUNK, BATCH), 256>>>();
    k_colreduce<<<dim3(9, BATCH), 256>>>();
    k_rowstats<<<dim3(288, BATCH), 256>>>();
    k_ygemm<<<dim3(36, 1, 8), 256>>>();
    k_post<<<dim3(36, 4, 8), 256>>>(x1, x2, out);
}

// round 2
// speedup vs baseline: 1.2645x; 1.2645x over previous
#include <cuda_runtime.h>
#include <math.h>
#include <stdint.h>

#define BATCH 4
#define CC 256
#define CI 128
#define NPIX 2304
#define BNEPS 1e-5f
#define NCHUNK 18
#define ETSPLIT 8

// ---------------- scratch ----------------
__device__ float g_PRE[4][BATCH][CI*NPIX];
__device__ float g_ETpart[BATCH][ETSPLIT][CI*CI];
__device__ float g_ET[BATCH][CI*CI];
__device__ float g_A1[BATCH][CI*CI];
__device__ float g_A2[BATCH][CI*CI];
__device__ float g_E[BATCH][NPIX*NPIX];
__device__ float g_Z[2][BATCH][CI*NPIX];
__device__ float g_Y[2][BATCH][CI*NPIX];
__device__ float g_colmax[BATCH][NPIX];
__device__ float g_colrsum[BATCH][NPIX];
__device__ float g_rowmax[BATCH][NPIX];
__device__ float g_rowrsum[BATCH][NPIX];
__device__ float g_pmax[BATCH][NCHUNK][NPIX];
__device__ float g_psum[BATCH][NCHUNK][NPIX];
__device__ float g_Wpre[4][CI*CC];
__device__ float g_bpre[4][CI];
__device__ float g_Wpost[2][CC*CI];
__device__ float g_bpost[2][CC];

// ---------------- tf32 helpers ----------------
__device__ __forceinline__ uint32_t f2t(float x) {
    uint32_t r;
    asm("cvt.rna.tf32.f32 %0, %1;" : "=r"(r) : "f"(x));
    return r;
}
__device__ __forceinline__ void f2t_split(float x, uint32_t& hi, uint32_t& lo) {
    hi = f2t(x);
    lo = f2t(x - __uint_as_float(hi));
}
__device__ __forceinline__ void mma8(float c[4], const uint32_t a[4], const uint32_t b[2]) {
    asm volatile(
        "mma.sync.aligned.m16n8k8.row.col.f32.tf32.tf32.f32 "
        "{%0,%1,%2,%3}, {%4,%5,%6,%7}, {%8,%9}, {%0,%1,%2,%3};"
        : "+f"(c[0]), "+f"(c[1]), "+f"(c[2]), "+f"(c[3])
        : "r"(a[0]), "r"(a[1]), "r"(a[2]), "r"(a[3]), "r"(b[0]), "r"(b[1]));
}

// ---------------- BN folding ----------------
__global__ void k_fold(const float* __restrict__ bn_pre, const float* __restrict__ w_pre,
                       const float* __restrict__ b_pre, const float* __restrict__ w_post,
                       const float* __restrict__ b_post, const float* __restrict__ bn_post)
{
    int tid = threadIdx.x;
    if (blockIdx.x == 0) {
        int i = tid >> 7, o = tid & 127;
        const float* bp = bn_pre + i * 4 * CC;
        const float* w  = w_pre + (i * CI + o) * CC;
        float acc = b_pre[i * CI + o];
        for (int c = 0; c < CC; c++) {
            float s = bp[c] * rsqrtf(bp[3 * CC + c] + BNEPS);
            float t = bp[CC + c] - bp[2 * CC + c] * s;
            float wv = w[c];
            g_Wpre[i][o * CC + c] = wv * s;
            acc += wv * t;
        }
        g_bpre[i][o] = acc;
    } else {
        int i = tid >> 8, o = tid & 255;
        const float* bp = bn_post + i * 4 * CC;
        float s = bp[o] * rsqrtf(bp[3 * CC + o] + BNEPS);
        const float* w = w_post + (i * CC + o) * CI;
        for (int c = 0; c < CI; c++)
            g_Wpost[i][o * CI + c] = w[c] * s;
        g_bpost[i][o] = b_post[i * CC + o] * s + bp[CC + o] - bp[2 * CC + o] * s;
    }
}

// ---------------- SIMT GEMM cores (unchanged) ----------------
__device__ __forceinline__ void mm16(float acc[4][4], const float ar[4], const float br[4])
{
#pragma unroll
    for (int r = 0; r < 4; r++)
#pragma unroll
        for (int c2 = 0; c2 < 4; c2++)
            acc[r][c2] = fmaf(ar[r], br[c2], acc[r][c2]);
}

__device__ __forceinline__ void nn_core64(const float* __restrict__ A, int lda,
                                          const float* __restrict__ Bm, int ldb,
                                          int K, int m0, int n0, float acc[4][4])
{
    __shared__ float As[16][68];
    __shared__ float Bs[16][64];
    const int tid = threadIdx.x;
    const int tx = tid & 15, ty = tid >> 4;
    const int ai = tid >> 2, aq = tid & 3;
    const int bk = tid >> 4, bj = (tid & 15) * 4;
    for (int k0 = 0; k0 < K; k0 += 16) {
        float4 av = *(const float4*)&A[(m0 + ai) * lda + k0 + aq * 4];
        As[aq*4+0][ai] = av.x; As[aq*4+1][ai] = av.y; As[aq*4+2][ai] = av.z; As[aq*4+3][ai] = av.w;
        *(float4*)&Bs[bk][bj] = *(const float4*)&Bm[(k0 + bk) * ldb + n0 + bj];
        __syncthreads();
#pragma unroll
        for (int k = 0; k < 16; k++) {
            float4 a4 = *(const float4*)&As[k][ty * 4];
            float4 b4 = *(const float4*)&Bs[k][tx * 4];
            float ar[4] = {a4.x, a4.y, a4.z, a4.w};
            float br[4] = {b4.x, b4.y, b4.z, b4.w};
            mm16(acc, ar, br);
        }
        __syncthreads();
    }
}

__device__ __forceinline__ void nt_core64(const float* __restrict__ A,
                                          const float* __restrict__ Bm, int ld,
                                          int kbeg, int kend, int m0, int n0, float acc[4][4])
{
    __shared__ float As[16][68];
    __shared__ float Bs[16][68];
    const int tid = threadIdx.x;
    const int tx = tid & 15, ty = tid >> 4;
    const int ri = tid >> 2, rq = tid & 3;
    for (int k0 = kbeg; k0 < kend; k0 += 16) {
        float4 av = *(const float4*)&A[(m0 + ri) * ld + k0 + rq * 4];
        As[rq*4+0][ri] = av.x; As[rq*4+1][ri] = av.y; As[rq*4+2][ri] = av.z; As[rq*4+3][ri] = av.w;
        float4 bv = *(const float4*)&Bm[(n0 + ri) * ld + k0 + rq * 4];
        Bs[rq*4+0][ri] = bv.x; Bs[rq*4+1][ri] = bv.y; Bs[rq*4+2][ri] = bv.z; Bs[rq*4+3][ri] = bv.w;
        __syncthreads();
#pragma unroll
        for (int k = 0; k < 16; k++) {
            float4 a4 = *(const float4*)&As[k][ty * 4];
            float4 b4 = *(const float4*)&Bs[k][tx * 4];
            float ar[4] = {a4.x, a4.y, a4.z, a4.w};
            float br[4] = {b4.x, b4.y, b4.z, b4.w};
            mm16(acc, ar, br);
        }
        __syncthreads();
    }
}

// ---------------- pre GEMMs ----------------
__global__ void __launch_bounds__(256) k_pre(const float* __restrict__ x1, const float* __restrict__ x2)
{
    int i = blockIdx.z >> 2, b = blockIdx.z & 3;
    int m0 = blockIdx.y * 64, n0 = blockIdx.x * 64;
    const float* Bm = ((i & 1) ? x2 : x1) + b * CC * NPIX;
    float acc[4][4] = {};
    nn_core64(g_Wpre[i], CC, Bm, NPIX, CC, m0, n0, acc);
    int tx = threadIdx.x & 15, ty = threadIdx.x >> 4;
    float* Cout = g_PRE[i][b];
#pragma unroll
    for (int r = 0; r < 4; r++) {
        int row = m0 + ty * 4 + r;
        float bias = g_bpre[i][row];
#pragma unroll
        for (int c2 = 0; c2 < 4; c2++)
            Cout[row * NPIX + n0 + tx * 4 + c2] = acc[r][c2] + bias;
    }
}

// ---------------- e_time split-K ----------------
__global__ void __launch_bounds__(256) k_etime()
{
    int b = blockIdx.z >> 3, ks = blockIdx.z & 7;
    int m0 = blockIdx.y * 64, n0 = blockIdx.x * 64;
    float acc[4][4] = {};
    const int chunk = NPIX / ETSPLIT;
    nt_core64(g_PRE[2][b], g_PRE[3][b], NPIX, ks * chunk, ks * chunk + chunk, m0, n0, acc);
    int tx = threadIdx.x & 15, ty = threadIdx.x >> 4;
    float* outp = g_ETpart[b][ks];
#pragma unroll
    for (int r = 0; r < 4; r++)
#pragma unroll
        for (int c2 = 0; c2 < 4; c2++)
            outp[(m0 + ty * 4 + r) * CI + n0 + tx * 4 + c2] = acc[r][c2];
}

__global__ void k_etreduce()
{
    int b = blockIdx.y, idx = blockIdx.x * 256 + threadIdx.x;
    float s = 0.f;
#pragma unroll
    for (int p = 0; p < ETSPLIT; p++) s += g_ETpart[b][p][idx];
    g_ET[b][idx] = s;
}

__global__ void k_softmax_time()
{
    int b = blockIdx.x, t = threadIdx.x;
    const float* ET = g_ET[b];
    float mx = -3.0e38f;
    for (int d = 0; d < CI; d++) mx = fmaxf(mx, ET[t * CI + d]);
    float s = 0.f;
    for (int d = 0; d < CI; d++) s += __expf(ET[t * CI + d] - mx);
    float rs = 1.f / s;
    for (int d = 0; d < CI; d++) g_A2[b][t * CI + d] = __expf(ET[t * CI + d] - mx) * rs;
    mx = -3.0e38f;
    for (int d = 0; d < CI; d++) mx = fmaxf(mx, ET[d * CI + t]);
    s = 0.f;
    for (int d = 0; d < CI; d++) s += __expf(ET[d * CI + t] - mx);
    rs = 1.f / s;
    for (int d = 0; d < CI; d++) g_A1[b][t * CI + d] = __expf(ET[d * CI + t] - mx) * rs;
}

// ---------------- Z GEMMs ----------------
__global__ void __launch_bounds__(256) k_zgemm()
{
    int zi = blockIdx.z >> 2, b = blockIdx.z & 3;
    int m0 = blockIdx.y * 64, n0 = blockIdx.x * 64;
    const float* A = zi ? g_A2[b] : g_A1[b];
    float acc[4][4] = {};
    nn_core64(A, CI, g_PRE[zi][b], NPIX, CI, m0, n0, acc);
    int tx = threadIdx.x & 15, ty = threadIdx.x >> 4;
    float* Zout = g_Z[zi][b];
#pragma unroll
    for (int r = 0; r < 4; r++)
#pragma unroll
        for (int c2 = 0; c2 < 4; c2++)
            Zout[(m0 + ty * 4 + r) * NPIX + n0 + tx * 4 + c2] = acc[r][c2];
}

// ======================================================================
// e_space via mma.sync tf32, 3-term emulation (near-fp32 accuracy)
// E[row0+r, col0+c] = sum_k T[k, row0+r] * P[k, col0+c],  K = 128
// Block tile 128(M) x 64(N), 8 warps (4x2), warp tile 32x32.
// SMEM: Ah/Al [32][136] (stride 8 mod 32 -> conflict-free frag loads),
//       Bh/Bl [32][72]
// ======================================================================
__global__ void __launch_bounds__(256) k_espace_mma()
{
    int b = blockIdx.z;
    int row0 = blockIdx.y * 128, col0 = blockIdx.x * 64;
    const float* __restrict__ T = g_PRE[2][b];
    const float* __restrict__ P = g_PRE[3][b];

    __shared__ uint32_t Ah[32][136], Al[32][136];
    __shared__ uint32_t Bh[32][72],  Bl[32][72];

    int tid = threadIdx.x;
    int wid = tid >> 5, lane = tid & 31;
    int g = lane >> 2, tig = lane & 3;
    int wm = (wid & 3) * 32, wn = (wid >> 2) * 32;

    float c[2][4][4] = {};

    for (int k0 = 0; k0 < CI; k0 += 32) {
        // A tile: T rows k0..k0+31, cols row0..row0+127
#pragma unroll
        for (int it = 0; it < 4; it++) {
            int v = tid + it * 256;
            int r = v >> 5, c4 = (v & 31) * 4;
            float4 t4 = *(const float4*)&T[(k0 + r) * NPIX + row0 + c4];
            uint32_t h0,l0,h1,l1,h2,l2,h3,l3;
            f2t_split(t4.x, h0, l0); f2t_split(t4.y, h1, l1);
            f2t_split(t4.z, h2, l2); f2t_split(t4.w, h3, l3);
            Ah[r][c4+0]=h0; Ah[r][c4+1]=h1; Ah[r][c4+2]=h2; Ah[r][c4+3]=h3;
            Al[r][c4+0]=l0; Al[r][c4+1]=l1; Al[r][c4+2]=l2; Al[r][c4+3]=l3;
        }
        // B tile: P rows k0..k0+31, cols col0..col0+63
#pragma unroll
        for (int it = 0; it < 2; it++) {
            int v = tid + it * 256;
            int r = v >> 4, c4 = (v & 15) * 4;
            float4 p4 = *(const float4*)&P[(k0 + r) * NPIX + col0 + c4];
            uint32_t h0,l0,h1,l1,h2,l2,h3,l3;
            f2t_split(p4.x, h0, l0); f2t_split(p4.y, h1, l1);
            f2t_split(p4.z, h2, l2); f2t_split(p4.w, h3, l3);
            Bh[r][c4+0]=h0; Bh[r][c4+1]=h1; Bh[r][c4+2]=h2; Bh[r][c4+3]=h3;
            Bl[r][c4+0]=l0; Bl[r][c4+1]=l1; Bl[r][c4+2]=l2; Bl[r][c4+3]=l3;
        }
        __syncthreads();
#pragma unroll
        for (int kk = 0; kk < 32; kk += 8) {
            uint32_t ah[2][4], al[2][4];
#pragma unroll
            for (int mi = 0; mi < 2; mi++) {
                int mr = wm + mi * 16;
                ah[mi][0] = Ah[kk+tig  ][mr + g    ];
                ah[mi][1] = Ah[kk+tig  ][mr + g + 8];
                ah[mi][2] = Ah[kk+tig+4][mr + g    ];
                ah[mi][3] = Ah[kk+tig+4][mr + g + 8];
                al[mi][0] = Al[kk+tig  ][mr + g    ];
                al[mi][1] = Al[kk+tig  ][mr + g + 8];
                al[mi][2] = Al[kk+tig+4][mr + g    ];
                al[mi][3] = Al[kk+tig+4][mr + g + 8];
            }
#pragma unroll
            for (int ni = 0; ni < 4; ni++) {
                uint32_t bh[2], bl[2];
                bh[0] = Bh[kk+tig  ][wn + ni*8 + g];
                bh[1] = Bh[kk+tig+4][wn + ni*8 + g];
                bl[0] = Bl[kk+tig  ][wn + ni*8 + g];
                bl[1] = Bl[kk+tig+4][wn + ni*8 + g];
#pragma unroll
                for (int mi = 0; mi < 2; mi++) {
                    mma8(c[mi][ni], ah[mi], bh);
                    mma8(c[mi][ni], ah[mi], bl);
                    mma8(c[mi][ni], al[mi], bh);
                }
            }
        }
        __syncthreads();
    }

    float* Ep = g_E[b];
#pragma unroll
    for (int mi = 0; mi < 2; mi++) {
#pragma unroll
        for (int ni = 0; ni < 4; ni++) {
            int row = row0 + wm + mi * 16 + g;
            int col = col0 + wn + ni * 8 + tig * 2;
            *(float2*)&Ep[row * NPIX + col]       = make_float2(c[mi][ni][0], c[mi][ni][1]);
            *(float2*)&Ep[(row + 8) * NPIX + col] = make_float2(c[mi][ni][2], c[mi][ni][3]);
        }
    }
}

// ---------------- e_space column stats ----------------
__global__ void k_colpart()
{
    int b = blockIdx.z, ch = blockIdx.y;
    int m = blockIdx.x * 256 + threadIdx.x;
    const float* Ep = g_E[b];
    float mx = -3.0e38f, s = 0.f;
    int n0 = ch * (NPIX / NCHUNK);
    for (int n = n0; n < n0 + NPIX / NCHUNK; n++) {
        float v = Ep[n * NPIX + m];
        if (v > mx) { s = s * __expf(mx - v) + 1.f; mx = v; }
        else        { s += __expf(v - mx); }
    }
    g_pmax[b][ch][m] = mx;
    g_psum[b][ch][m] = s;
}

__global__ void k_colreduce()
{
    int b = blockIdx.y, m = blockIdx.x * 256 + threadIdx.x;
    float mx = -3.0e38f, s = 0.f;
#pragma unroll
    for (int ch = 0; ch < NCHUNK; ch++) {
        float pm = g_pmax[b][ch][m], ps = g_psum[b][ch][m];
        float nm = fmaxf(mx, pm);
        s = s * __expf(mx - nm) + ps * __expf(pm - nm);
        mx = nm;
    }
    g_colmax[b][m] = mx;
    g_colrsum[b][m] = 1.f / s;
}

__global__ void k_rowstats()
{
    int b = blockIdx.y;
    int n = blockIdx.x * 8 + (threadIdx.x >> 5);
    int lane = threadIdx.x & 31;
    const float* row = g_E[b] + n * NPIX;
    float mx = -3.0e38f, s = 0.f;
    for (int m = lane; m < NPIX; m += 32) {
        float v = row[m];
        if (v > mx) { s = s * __expf(mx - v) + 1.f; mx = v; }
        else        { s += __expf(v - mx); }
    }
#pragma unroll
    for (int off = 16; off; off >>= 1) {
        float om = __shfl_xor_sync(0xffffffffu, mx, off);
        float os = __shfl_xor_sync(0xffffffffu, s, off);
        float nm = fmaxf(mx, om);
        s = s * __expf(mx - nm) + os * __expf(om - nm);
        mx = nm;
    }
    if (lane == 0) { g_rowmax[b][n] = mx; g_rowrsum[b][n] = 1.f / s; }
}

// ======================================================================
// Y GEMMs via mma.sync tf32 (single pass) with fused softmax B-load.
// y[c, m] = sum_n Z[c,n] * expS[n, m]
// Block tile 128(M=CI) x 128(N), 16 warps (4x4), warp tile 32x32, K chunk 32.
// A (Z) in SMEM [m][k] stride 36; B: yi=0 -> [k][n] stride 136 (E rows are
// k-major), yi=1 -> [n][k] stride 36 (E rows are n-major; col-major B == [n][k]).
// ======================================================================
__global__ void __launch_bounds__(512) k_ygemm_mma()
{
    int yi = blockIdx.z >> 2, b = blockIdx.z & 3;
    int n0 = blockIdx.x * 128;
    const float* __restrict__ Zp = g_Z[yi][b];
    const float* __restrict__ Ep = g_E[b];
    const float* __restrict__ vmax = yi ? g_rowmax[b]  : g_colmax[b];
    const float* __restrict__ vrs  = yi ? g_rowrsum[b] : g_colrsum[b];

    __shared__ uint32_t As[128][36];
    __shared__ uint32_t BsRaw[128 * 36];   // also viewed as [32][136] (4352 <= 4608)
    __shared__ float s_max[128], s_rs[128];

    int tid = threadIdx.x;
    if (tid < 128) { s_max[tid] = vmax[n0 + tid]; s_rs[tid] = vrs[n0 + tid]; }
    __syncthreads();

    int wid = tid >> 5, lane = tid & 31;
    int g = lane >> 2, tig = lane & 3;
    int wm = (wid & 3) * 32, wn = (wid >> 2) * 32;

    float c[2][4][4] = {};

    for (int k0 = 0; k0 < NPIX; k0 += 32) {
        // A tile: Z[0..127][k0..k0+31]
#pragma unroll
        for (int it = 0; it < 2; it++) {
            int v = tid + it * 512;
            int m = v >> 3, kq = (v & 7) * 4;
            float4 z4 = *(const float4*)&Zp[m * NPIX + k0 + kq];
            As[m][kq+0] = f2t(z4.x); As[m][kq+1] = f2t(z4.y);
            As[m][kq+2] = f2t(z4.z); As[m][kq+3] = f2t(z4.w);
        }
        // B tile with fused exp
        if (yi == 0) {
#pragma unroll
            for (int it = 0; it < 2; it++) {
                int v = tid + it * 512;
                int kk = v >> 5, jq = (v & 31) * 4;
                float4 e4 = *(const float4*)&Ep[(k0 + kk) * NPIX + n0 + jq];
                uint32_t* brow = &BsRaw[kk * 136];
                brow[jq+0] = f2t(__expf(e4.x - s_max[jq+0]));
                brow[jq+1] = f2t(__expf(e4.y - s_max[jq+1]));
                brow[jq+2] = f2t(__expf(e4.z - s_max[jq+2]));
                brow[jq+3] = f2t(__expf(e4.w - s_max[jq+3]));
            }
        } else {
#pragma unroll
            for (int it = 0; it < 2; it++) {
                int v = tid + it * 512;
                int j = v >> 3, kq = (v & 7) * 4;
                float4 e4 = *(const float4*)&Ep[(n0 + j) * NPIX + k0 + kq];
                float mxj = s_max[j];
                uint32_t* brow = &BsRaw[j * 36];
                brow[kq+0] = f2t(__expf(e4.x - mxj));
                brow[kq+1] = f2t(__expf(e4.y - mxj));
                brow[kq+2] = f2t(__expf(e4.z - mxj));
                brow[kq+3] = f2t(__expf(e4.w - mxj));
            }
        }
        __syncthreads();
#pragma unroll
        for (int kk = 0; kk < 32; kk += 8) {
            uint32_t a[2][4];
#pragma unroll
            for (int mi = 0; mi < 2; mi++) {
                int mr = wm + mi * 16;
                a[mi][0] = As[mr + g    ][kk + tig    ];
                a[mi][1] = As[mr + g + 8][kk + tig    ];
                a[mi][2] = As[mr + g    ][kk + tig + 4];
                a[mi][3] = As[mr + g + 8][kk + tig + 4];
            }
#pragma unroll
            for (int ni = 0; ni < 4; ni++) {
                uint32_t bb[2];
                if (yi == 0) {
                    bb[0] = BsRaw[(kk + tig    ) * 136 + wn + ni*8 + g];
                    bb[1] = BsRaw[(kk + tig + 4) * 136 + wn + ni*8 + g];
                } else {
                    bb[0] = BsRaw[(wn + ni*8 + g) * 36 + kk + tig    ];
                    bb[1] = BsRaw[(wn + ni*8 + g) * 36 + kk + tig + 4];
                }
                mma8(c[0][ni], a[0], bb);
                mma8(c[1][ni], a[1], bb);
            }
        }
        __syncthreads();
    }

    float* Yp = g_Y[yi][b];
#pragma unroll
    for (int mi = 0; mi < 2; mi++) {
#pragma unroll
        for (int ni = 0; ni < 4; ni++) {
            int row = wm + mi * 16 + g;
            int col = wn + ni * 8 + tig * 2;
            float r0 = s_rs[col], r1 = s_rs[col + 1];
            *(float2*)&Yp[row * NPIX + n0 + col] =
                make_float2(c[mi][ni][0] * r0, c[mi][ni][1] * r1);
            *(float2*)&Yp[(row + 8) * NPIX + n0 + col] =
                make_float2(c[mi][ni][2] * r0, c[mi][ni][3] * r1);
        }
    }
}

// ---------------- post GEMM + bias + residual ----------------
__global__ void __launch_bounds__(256) k_post(const float* __restrict__ x1,
                                              const float* __restrict__ x2,
                                              float* __restrict__ out)
{
    int i = blockIdx.z >> 2, b = blockIdx.z & 3;
    int m0 = blockIdx.y * 64, n0 = blockIdx.x * 64;
    float acc[4][4] = {};
    nn_core64(g_Wpost[i], CI, g_Y[i][b], NPIX, CI, m0, n0, acc);
    int tx = threadIdx.x & 15, ty = threadIdx.x >> 4;
    const float* xs = (i ? x2 : x1) + b * CC * NPIX;
    float* op = out + (size_t)i * BATCH * CC * NPIX + (size_t)b * CC * NPIX;
#pragma unroll
    for (int r = 0; r < 4; r++) {
        int row = m0 + ty * 4 + r;
        float bias = g_bpost[i][row];
#pragma unroll
        for (int c2 = 0; c2 < 4; c2++) {
            int col = n0 + tx * 4 + c2;
            op[row * NPIX + col] = acc[r][c2] + bias + xs[row * NPIX + col];
        }
    }
}

// ---------------- launcher ----------------
extern "C" void kernel_launch(void* const* d_in, const int* in_sizes, int n_in,
                              void* d_out, int out_size)
{
    const float* x1      = (const float*)d_in[0];
    const float* x2      = (const float*)d_in[1];
    const float* bn_pre  = (const float*)d_in[2];
    const float* w_pre   = (const float*)d_in[3];
    const float* b_pre   = (const float*)d_in[4];
    const float* w_post  = (const float*)d_in[5];
    const float* b_post  = (const float*)d_in[6];
    const float* bn_post = (const float*)d_in[7];
    float* out = (float*)d_out;

    k_fold<<<2, 512>>>(bn_pre, w_pre, b_pre, w_post, b_post, bn_post);
    k_pre<<<dim3(36, 2, 16), 256>>>(x1, x2);
    k_etime<<<dim3(2, 2, BATCH * ETSPLIT), 256>>>();
    k_etreduce<<<dim3(64, BATCH), 256>>>();
    k_softmax_time<<<BATCH, 128>>>();
    k_espace_mma<<<dim3(36, 18, BATCH), 256>>>();
    k_zgemm<<<dim3(36, 2, 8), 256>>>();
    k_colpart<<<dim3(9, NCHUNK, BATCH), 256>>>();
    k_colreduce<<<dim3(9, BATCH), 256>>>();
    k_rowstats<<<dim3(288, BATCH), 256>>>();
    k_ygemm_mma<<<dim3(18, 1, 8), 512>>>();
    k_post<<<dim3(36, 4, 8), 256>>>(x1, x2, out);
}